// round 11
// baseline (speedup 1.0000x reference)
#include <cuda_runtime.h>
#include <cuda_bf16.h>
#include <cstdint>
#include <math.h>

// Normalized embeddings scratch (bf16): 8192 * 256 * 2B = 4 MB, L2-resident.
__device__ __nv_bfloat16 g_en[8192 * 256];
// Dynamic tile counter for the persistent loss kernel (reset each launch).
__device__ int g_tile_ctr;

#define NPERSIST 296        // 2 CTAs x 148 SMs

// ---------------------------------------------------------------------------
// Kernel 1: row-normalize embeddings (fp32 -> bf16). One warp per row, D=256.
// Also zeroes the (poisoned) output scalar and resets the tile counter.
// ---------------------------------------------------------------------------
__global__ void normalize_kernel(const float* __restrict__ emb, int B,
                                 float* __restrict__ out) {
    if (blockIdx.x == 0 && threadIdx.x == 0) {
        out[0] = 0.0f;
        g_tile_ctr = NPERSIST;
    }

    const int warpId = threadIdx.x >> 5;
    const int lane   = threadIdx.x & 31;
    const int row    = blockIdx.x * 8 + warpId;
    if (row >= B) return;

    const float4* p = reinterpret_cast<const float4*>(emb + (size_t)row * 256);
    float4 v0 = p[lane];
    float4 v1 = p[lane + 32];

    float ss = v0.x * v0.x + v0.y * v0.y + v0.z * v0.z + v0.w * v0.w
             + v1.x * v1.x + v1.y * v1.y + v1.z * v1.z + v1.w * v1.w;
    #pragma unroll
    for (int o = 16; o > 0; o >>= 1) ss += __shfl_xor_sync(0xffffffffu, ss, o);

    const float scale = 1.0f / fmaxf(sqrtf(ss), 1e-8f);

    __nv_bfloat162 a0 = __floats2bfloat162_rn(v0.x * scale, v0.y * scale);
    __nv_bfloat162 a1 = __floats2bfloat162_rn(v0.z * scale, v0.w * scale);
    __nv_bfloat162 b0 = __floats2bfloat162_rn(v1.x * scale, v1.y * scale);
    __nv_bfloat162 b1 = __floats2bfloat162_rn(v1.z * scale, v1.w * scale);

    uint2 ua, ub;
    ua.x = *reinterpret_cast<unsigned*>(&a0);
    ua.y = *reinterpret_cast<unsigned*>(&a1);
    ub.x = *reinterpret_cast<unsigned*>(&b0);
    ub.y = *reinterpret_cast<unsigned*>(&b1);

    uint2* orow = reinterpret_cast<uint2*>(g_en + (size_t)row * 256);
    orow[lane]      = ua;
    orow[lane + 32] = ub;
}

// ---------------------------------------------------------------------------
// Kernel 2: PERSISTENT fused cos-GEMM + |text - cos| masked reduction.
// 296 resident CTAs pull 128x128 upper-tri tiles from a global counter.
// Per tile: K=256 as four K=64 chunks, two operand buffers (roles swap per
// tile), text0 -> dedicated region, text1 -> chunk-A buffer after its last
// read. The cp.async commit ladder extends ACROSS tiles: next tile's ch0 is
// staged during the current epilogue wait; ch1 + text0 after the epilogue's
// last smem read. In-order group retirement makes every wait_group N retire
// exactly the group that wait needs:
//   queue [ch0,ch1,text0] -> w2(ch0) w2(ch1) w1(text0+ch2) w1(ch3) w1(text1)
// smem = 2*36864 + 33792 = 105 KB -> 2 CTAs/SM.
// ---------------------------------------------------------------------------
#define LDM_OP     72                      // bf16 elems per padded chunk row
#define ROW_BYTES  144
#define STRIP_B    (128 * ROW_BYTES)       // 18432
#define BUF_B      (2 * STRIP_B)           // 36864 (A strip + B strip)
#define LDM_T      132                     // fp32 elems per padded text row
#define TROW_B     528
#define TEXT0_OFF  (2 * BUF_B)             // 73728
#define TEXT_HALF_B (64 * TROW_B)          // 33792
#define SMEM_TOTAL  (TEXT0_OFF + TEXT_HALF_B)   // 107520

#define LDSM4(R0, R1, R2, R3, ADDR)                                          \
    asm volatile("ldmatrix.sync.aligned.m8n8.x4.shared.b16 {%0,%1,%2,%3}, [%4];" \
                 : "=r"(R0), "=r"(R1), "=r"(R2), "=r"(R3) : "r"(ADDR))

#define MMA16816(C, A, B0, B1)                                               \
    asm volatile("mma.sync.aligned.m16n8k16.row.col.f32.bf16.bf16.f32 "      \
                 "{%0,%1,%2,%3}, {%4,%5,%6,%7}, {%8,%9}, {%0,%1,%2,%3};"     \
                 : "+f"((C)[0]), "+f"((C)[1]), "+f"((C)[2]), "+f"((C)[3])    \
                 : "r"((A)[0]), "r"((A)[1]), "r"((A)[2]), "r"((A)[3]),       \
                   "r"(B0), "r"(B1))

#define CP16(S, G)                                                           \
    asm volatile("cp.async.cg.shared.global [%0], [%1], 16;"                 \
                 :: "r"(S), "l"(G) : "memory")
#define COMMIT() asm volatile("cp.async.commit_group;" ::: "memory")
#define WAITG(N) asm volatile("cp.async.wait_group %0;" :: "n"(N) : "memory")

// Stage one K=64 operand chunk (A + B strips) into buffer at `dst`, commit.
__device__ __forceinline__ void stage_chunk(uint32_t dst, int ch,
                                            const char* Ag, const char* Bg,
                                            int tid) {
    const size_t gchunk = (size_t)ch * 128;
    #pragma unroll
    for (int i = tid; i < 1024; i += 256) {           // 128 rows x 8 x 16B
        const int r = i >> 3;
        const int c = i & 7;
        const uint32_t soff = (uint32_t)r * ROW_BYTES + (uint32_t)c * 16;
        const size_t   goff = (size_t)r * 512 + gchunk + (size_t)c * 16;
        CP16(dst + soff, Ag + goff);
        CP16(dst + STRIP_B + soff, Bg + goff);
    }
    COMMIT();
}

// Stage 64 text rows (128 floats each) into smem at `dst` (528 B rows), commit.
__device__ __forceinline__ void stage_text_half(uint32_t dst, const char* tg,
                                                int B, int tid) {
    #pragma unroll
    for (int i = tid; i < 2048; i += 256) {           // 64 rows x 32 x 16B
        const int r = i >> 5;
        const int c = i & 31;
        CP16(dst + (uint32_t)r * TROW_B + (uint32_t)c * 16,
             tg + (size_t)r * B * 4 + (size_t)c * 16);
    }
    COMMIT();
}

// One K=64 chunk of MMAs from buffer at `bufBase`.
__device__ __forceinline__ void mma_chunk(uint32_t bufBase, uint32_t aOff,
                                          uint32_t bOff, float c[2][8][4]) {
    #pragma unroll
    for (int kc = 0; kc < 4; kc++) {
        const uint32_t koff = (uint32_t)(kc * 32);    // 16 bf16 = 32 B
        uint32_t a[2][4];
        #pragma unroll
        for (int mt = 0; mt < 2; mt++)
            LDSM4(a[mt][0], a[mt][1], a[mt][2], a[mt][3],
                  bufBase + aOff + (uint32_t)(mt * 16 * ROW_BYTES) + koff);
        uint32_t b[4][4];
        #pragma unroll
        for (int p = 0; p < 4; p++)
            LDSM4(b[p][0], b[p][1], b[p][2], b[p][3],
                  bufBase + bOff + (uint32_t)(p * 16 * ROW_BYTES) + koff);
        #pragma unroll
        for (int mt = 0; mt < 2; mt++)
            #pragma unroll
            for (int nt = 0; nt < 8; nt++)
                MMA16816(c[mt][nt], a[mt],
                         b[nt >> 1][(nt & 1) * 2], b[nt >> 1][(nt & 1) * 2 + 1]);
    }
}

// tile id -> (by, bx) with by <= bx
__device__ __forceinline__ void tile_coords(int t, int NT, int& by, int& bx) {
    int b = 0;
    while (t >= NT - b) { t -= NT - b; ++b; }
    by = b; bx = b + t;
}

__global__ __launch_bounds__(256, 2)
void loss_kernel(const float* __restrict__ text, float* __restrict__ out,
                 int B, float scale, int ntiles) {
    extern __shared__ char smem[];
    uint32_t sbase;
    asm("{ .reg .u64 t; cvta.to.shared.u64 t, %1; cvt.u32.u64 %0, t; }"
        : "=r"(sbase) : "l"((const void*)smem));

    const int tid = threadIdx.x;
    const int NT = B >> 7;

    __shared__ int s_next;
    __shared__ float red[8];

    // ---- warp / fragment geometry ----
    const int warpId = tid >> 5;
    const int lane   = tid & 31;
    const int wr = warpId & 3;    // 32-row strip
    const int wc = warpId >> 2;   // 64-col strip
    const int grp = lane >> 3;

    const uint32_t aOff =
        (uint32_t)(((wr * 32 + (lane & 15)) * LDM_OP + (lane >> 4) * 8) * 2);
    const uint32_t bOff = (uint32_t)STRIP_B +
        (uint32_t)(((wc * 64 + (grp >> 1) * 8 + (lane & 7)) * LDM_OP + (grp & 1) * 8) * 2);

    // ---- buffer roles (byte offsets from sbase); swap each tile ----
    uint32_t bufA = 0, bufB = BUF_B;

    int t = blockIdx.x;
    if (t >= ntiles) return;

    // ---- prologue: stage tile t's ch0 -> bufA, ch1 -> bufB, text0 -> T ----
    {
        int by, bx;
        tile_coords(t, NT, by, bx);
        const char* Ag = reinterpret_cast<const char*>(g_en + (size_t)by * 32768);
        const char* Bg = reinterpret_cast<const char*>(g_en + (size_t)bx * 32768);
        const char* tg = reinterpret_cast<const char*>(
            text + (size_t)(by * 128) * B + (size_t)bx * 128);
        stage_chunk(sbase + bufA, 0, Ag, Bg, tid);
        stage_chunk(sbase + bufB, 1, Ag, Bg, tid);
        stage_text_half(sbase + TEXT0_OFF, tg, B, tid);
    }

    while (true) {
        int by, bx;
        tile_coords(t, NT, by, bx);
        const char* Ag = reinterpret_cast<const char*>(g_en + (size_t)by * 32768);
        const char* Bg = reinterpret_cast<const char*>(g_en + (size_t)bx * 32768);
        const char* tg = reinterpret_cast<const char*>(
            text + (size_t)(by * 128) * B + (size_t)bx * 128);

        float c[2][8][4];
        #pragma unroll
        for (int mt = 0; mt < 2; mt++)
            #pragma unroll
            for (int nt = 0; nt < 8; nt++)
                #pragma unroll
                for (int e = 0; e < 4; e++) c[mt][nt][e] = 0.0f;

        // ---- ch0 ----
        WAITG(2); __syncthreads();
        if (tid == 0) s_next = atomicAdd(&g_tile_ctr, 1);
        mma_chunk(sbase + bufA, aOff, bOff, c);
        __syncthreads();
        stage_chunk(sbase + bufA, 2, Ag, Bg, tid);            // ch2 -> bufA

        // ---- ch1 ----
        WAITG(2); __syncthreads();
        mma_chunk(sbase + bufB, aOff, bOff, c);
        __syncthreads();
        stage_chunk(sbase + bufB, 3, Ag, Bg, tid);            // ch3 -> bufB

        // ---- ch2 (wait also retires text0: in-order) ----
        WAITG(1); __syncthreads();
        mma_chunk(sbase + bufA, aOff, bOff, c);
        __syncthreads();
        stage_text_half(sbase + bufA, tg + (size_t)64 * B * 4, B, tid); // text1

        // ---- ch3 ----
        WAITG(1); __syncthreads();
        mma_chunk(sbase + bufB, aOff, bOff, c);
        __syncthreads();                                      // s_next published

        // ---- stage next tile's ch0 -> bufB (overlaps epilogue wait) ----
        const int tn  = s_next;
        const int tcl = (tn < ntiles) ? tn : 0;
        int byn, bxn;
        tile_coords(tcl, NT, byn, bxn);
        const char* Agn = reinterpret_cast<const char*>(g_en + (size_t)byn * 32768);
        const char* Bgn = reinterpret_cast<const char*>(g_en + (size_t)bxn * 32768);
        const char* tgn = reinterpret_cast<const char*>(
            text + (size_t)(byn * 128) * B + (size_t)bxn * 128);
        stage_chunk(sbase + bufB, 0, Agn, Bgn, tid);

        // ---- epilogue: text1 ready (in-order retirement of its group) ----
        WAITG(1); __syncthreads();

        const int qrow = lane >> 2;
        const int qcol = (lane & 3) * 2;
        const bool diag = (bx == by);
        const float* __restrict__ Ts = reinterpret_cast<const float*>(
            smem + (wr < 2 ? (uint32_t)TEXT0_OFF : bufA));

        float acc = 0.0f;
        #pragma unroll
        for (int mt = 0; mt < 2; mt++) {
            const int r0 = wr * 32 + mt * 16 + qrow;
            const int lr = r0 & 63;
            #pragma unroll
            for (int nt = 0; nt < 8; nt++) {
                const int cc = wc * 64 + nt * 8 + qcol;
                const float2 t0 = *reinterpret_cast<const float2*>(Ts + lr * LDM_T + cc);
                const float2 t1 = *reinterpret_cast<const float2*>(Ts + (lr + 8) * LDM_T + cc);
                const float* cf = c[mt][nt];
                if (!diag) {
                    acc += fabsf(t0.x - cf[0]) + fabsf(t0.y - cf[1])
                         + fabsf(t1.x - cf[2]) + fabsf(t1.y - cf[3]);
                } else {
                    if (cc     > r0)     acc += fabsf(t0.x - cf[0]);
                    if (cc + 1 > r0)     acc += fabsf(t0.y - cf[1]);
                    if (cc     > r0 + 8) acc += fabsf(t1.x - cf[2]);
                    if (cc + 1 > r0 + 8) acc += fabsf(t1.y - cf[3]);
                }
            }
        }

        #pragma unroll
        for (int o = 16; o > 0; o >>= 1) acc += __shfl_xor_sync(0xffffffffu, acc, o);
        if (lane == 0) red[warpId] = acc;
        __syncthreads();    // also: all smem reads of T/bufA done
        if (tid == 0) {
            float s = 0.0f;
            #pragma unroll
            for (int w = 0; w < 8; w++) s += red[w];
            atomicAdd(out, s * scale);
        }

        // ---- stage next tile's ch1 -> bufA and text0 -> T ----
        stage_chunk(sbase + bufA, 1, Agn, Bgn, tid);
        stage_text_half(sbase + TEXT0_OFF, tgn, B, tid);

        // swap buffer roles; advance
        const uint32_t tmp = bufA; bufA = bufB; bufB = tmp;
        t = tn;
        if (t >= ntiles) { WAITG(0); break; }
    }
}

// ---------------------------------------------------------------------------
// Launch
// ---------------------------------------------------------------------------
extern "C" void kernel_launch(void* const* d_in, const int* in_sizes, int n_in,
                              void* d_out, int out_size) {
    const float* emb  = (const float*)d_in[0];   // [B, D] fp32
    const float* text = (const float*)d_in[1];   // [B, B] fp32
    float* out = (float*)d_out;

    const int B = (int)(sqrt((double)in_sizes[1]) + 0.5);   // 8192
    const double count = (double)B * (double)(B - 1) / 2.0;
    const float scale = (float)(0.1 / count);

    cudaFuncSetAttribute(loss_kernel,
                         cudaFuncAttributeMaxDynamicSharedMemorySize, SMEM_TOTAL);

    normalize_kernel<<<B / 8, 256>>>(emb, B, out);

    const int NT = B / 128;
    const int ntiles = NT * (NT + 1) / 2;   // 2080 upper-tri tiles
    loss_kernel<<<NPERSIST, 256, SMEM_TOTAL>>>(text, out, B, scale, ntiles);
}